// round 1
// baseline (speedup 1.0000x reference)
#include <cuda_runtime.h>
#include <cstdint>

// Problem constants
#define BB     8
#define HEADS  8
#define NPOS   4096          // 64*64
#define WIMG   64
#define HD     64            // head dim
#define DIMM   512
#define INNER  512           // HEADS*HD
#define QKV3   1536          // 3*INNER

// Scratch (allocation-free rule: __device__ globals)
__device__ float g_qkv[(size_t)BB * NPOS * QKV3];    // [b, n, 1536]  (q|k|v)
__device__ float g_attn[(size_t)BB * NPOS * INNER];  // [b, n, 512]

// ---------------------------------------------------------------------------
// Tiled fp32 GEMM: C[M,N] = A[M,K] @ B[K,N] (+ bias), row-major.
// BM=BN=128, BK=8, TM=TN=8, 256 threads.
// ---------------------------------------------------------------------------
template <int BM, int BN, int BK, int TM, int TN>
__global__ void __launch_bounds__((BM * BN) / (TM * TN))
sgemm_kernel(int M, int N, int K,
             const float* __restrict__ A,
             const float* __restrict__ B,
             float* __restrict__ C,
             const float* __restrict__ bias)
{
    const int cRow = blockIdx.y;
    const int cCol = blockIdx.x;

    const int threadCol = threadIdx.x % (BN / TN);  // 0..15
    const int threadRow = threadIdx.x / (BN / TN);  // 0..15

    __shared__ float As[BK][BM];
    __shared__ float Bs[BK][BN];

    const float* Ap = A + (size_t)cRow * BM * K;
    const float* Bp = B + cCol * BN;

    // A tile load mapping (float4 along K): 256 threads, BK/4 = 2 lanes per row
    const int innerRowA = threadIdx.x / (BK / 4);        // 0..127
    const int innerColA = threadIdx.x % (BK / 4);        // 0..1
    // B tile load mapping: BN/4 = 32 lanes per row
    const int innerRowB = threadIdx.x / (BN / 4);        // 0..7
    const int innerColB = threadIdx.x % (BN / 4);        // 0..31

    float acc[TM * TN];
    #pragma unroll
    for (int i = 0; i < TM * TN; i++) acc[i] = 0.f;
    float regM[TM], regN[TN];

    for (int bk = 0; bk < K; bk += BK) {
        // load A tile (transposed into As[k][m])
        float4 ta = *reinterpret_cast<const float4*>(
            &Ap[(size_t)innerRowA * K + innerColA * 4]);
        As[innerColA * 4 + 0][innerRowA] = ta.x;
        As[innerColA * 4 + 1][innerRowA] = ta.y;
        As[innerColA * 4 + 2][innerRowA] = ta.z;
        As[innerColA * 4 + 3][innerRowA] = ta.w;
        // load B tile
        *reinterpret_cast<float4*>(&Bs[innerRowB][innerColB * 4]) =
            *reinterpret_cast<const float4*>(&Bp[(size_t)innerRowB * N + innerColB * 4]);
        __syncthreads();

        Ap += BK;
        Bp += (size_t)BK * N;

        #pragma unroll
        for (int k = 0; k < BK; ++k) {
            #pragma unroll
            for (int i = 0; i < TM; i++) regM[i] = As[k][threadRow * TM + i];
            #pragma unroll
            for (int j = 0; j < TN; j++) regN[j] = Bs[k][threadCol * TN + j];
            #pragma unroll
            for (int i = 0; i < TM; i++)
                #pragma unroll
                for (int j = 0; j < TN; j++)
                    acc[i * TN + j] += regM[i] * regN[j];
        }
        __syncthreads();
    }

    // epilogue
    #pragma unroll
    for (int i = 0; i < TM; i++) {
        const size_t row = (size_t)cRow * BM + threadRow * TM + i;
        #pragma unroll
        for (int j = 0; j < TN; j += 4) {
            const int col = cCol * BN + threadCol * TN + j;
            float4 t;
            t.x = acc[i * TN + j + 0];
            t.y = acc[i * TN + j + 1];
            t.z = acc[i * TN + j + 2];
            t.w = acc[i * TN + j + 3];
            if (bias != nullptr) {
                t.x += bias[col + 0];
                t.y += bias[col + 1];
                t.z += bias[col + 2];
                t.w += bias[col + 3];
            }
            *reinterpret_cast<float4*>(&C[row * N + col]) = t;
        }
    }
}

// ---------------------------------------------------------------------------
// 3x3 neighborhood attention. One warp per (b, h, n).
// Zero-pad semantics: OOB neighbor -> dot = 0 (participates in softmax),
// value contribution = 0.
// ---------------------------------------------------------------------------
__global__ void __launch_bounds__(256)
attn_kernel()
{
    const int warp = (blockIdx.x * blockDim.x + threadIdx.x) >> 5;
    const int lane = threadIdx.x & 31;

    // warp -> (b, h, n): n innermost for k/v L2 reuse across neighboring queries
    const int n = warp & (NPOS - 1);
    const int h = (warp >> 12) & (HEADS - 1);
    const int b = warp >> 15;

    const float scale = 0.125f;  // 64^-0.5
    const int d0 = lane * 2;

    const size_t rowbase = ((size_t)(b * NPOS + n)) * QKV3;
    const float2 q2 = *reinterpret_cast<const float2*>(&g_qkv[rowbase + h * HD + d0]);

    const int y = n >> 6;
    const int x = n & 63;

    float dots[9];
    int   nidx[9];
    #pragma unroll
    for (int j = 0; j < 9; j++) {
        const int dy = j / 3 - 1, dx = j % 3 - 1;
        const int yy = y + dy, xx = x + dx;
        const bool ok = ((unsigned)yy < (unsigned)WIMG) && ((unsigned)xx < (unsigned)WIMG);
        const int nn = yy * WIMG + xx;
        nidx[j] = ok ? nn : -1;
        float p = 0.f;
        if (ok) {
            const float2 k2 = *reinterpret_cast<const float2*>(
                &g_qkv[((size_t)(b * NPOS + nn)) * QKV3 + INNER + h * HD + d0]);
            p = q2.x * k2.x + q2.y * k2.y;
        }
        #pragma unroll
        for (int off = 16; off; off >>= 1)
            p += __shfl_xor_sync(0xffffffffu, p, off);
        dots[j] = p * scale;   // exactly 0 for zero-padded OOB neighbors
    }

    // softmax over 9 (redundant per lane)
    float m = dots[0];
    #pragma unroll
    for (int j = 1; j < 9; j++) m = fmaxf(m, dots[j]);
    float e[9];
    float s = 0.f;
    #pragma unroll
    for (int j = 0; j < 9; j++) { e[j] = __expf(dots[j] - m); s += e[j]; }
    const float inv = 1.f / s;

    float2 accv = make_float2(0.f, 0.f);
    #pragma unroll
    for (int j = 0; j < 9; j++) {
        if (nidx[j] >= 0) {
            const float2 v2 = *reinterpret_cast<const float2*>(
                &g_qkv[((size_t)(b * NPOS + nidx[j])) * QKV3 + 2 * INNER + h * HD + d0]);
            const float a = e[j] * inv;
            accv.x += a * v2.x;
            accv.y += a * v2.y;
        }
    }

    *reinterpret_cast<float2*>(
        &g_attn[((size_t)(b * NPOS + n)) * INNER + h * HD + d0]) = accv;
}

// ---------------------------------------------------------------------------
// Launch
// ---------------------------------------------------------------------------
extern "C" void kernel_launch(void* const* d_in, const int* in_sizes, int n_in,
                              void* d_out, int out_size)
{
    const float* x     = (const float*)d_in[0];
    const float* w_qkv = (const float*)d_in[1];
    const float* w_out = (const float*)d_in[2];
    const float* b_out = (const float*)d_in[3];
    float* out = (float*)d_out;

    float* qkv  = nullptr;
    float* attn = nullptr;
    cudaGetSymbolAddress((void**)&qkv,  g_qkv);
    cudaGetSymbolAddress((void**)&attn, g_attn);

    const int M = BB * NPOS;  // 32768

    // GEMM1: qkv = x @ w_qkv   [32768,512] x [512,1536]
    {
        dim3 grid(QKV3 / 128, M / 128);   // (12, 256)
        sgemm_kernel<128, 128, 8, 8, 8><<<grid, 256>>>(
            M, QKV3, DIMM, x, w_qkv, qkv, nullptr);
    }

    // Attention: one warp per (b,h,n) -> 262144 warps, 8 warps/block
    {
        const int totalWarps = BB * HEADS * NPOS;
        attn_kernel<<<totalWarps / 8, 256>>>();
    }

    // GEMM2: out = attn @ w_out + b_out   [32768,512] x [512,512]
    {
        dim3 grid(DIMM / 128, M / 128);   // (4, 256)
        sgemm_kernel<128, 128, 8, 8, 8><<<grid, 256>>>(
            M, DIMM, INNER, attn, w_out, out, b_out);
    }
}

// round 4
// speedup vs baseline: 1.8975x; 1.8975x over previous
#include <cuda_runtime.h>
#include <cuda_fp16.h>
#include <cstdint>

// Problem constants
#define BB     8
#define HEADS  8
#define NPOS   4096          // 64*64
#define WIMG   64
#define HD     64
#define DIMM   512
#define INNER  512
#define QKV3   1536
#define MTOT   (BB * NPOS)   // 32768
#define KDIM   512

#define STAGE_BYTES 32768          // A 16KB + B 16KB (128x64 fp16 each)
#define NSTAGES     4
#define KSTEPS      24             // 3 groups * (512/64)
#define GEMM_SMEM   (1024 + NSTAGES * STAGE_BYTES)

#define SMEM_SWIZZLE_128B(off) ((off) ^ (((off) >> 3) & 0x70))

// ---------------------------------------------------------------------------
// Scratch (__device__ globals; allocation is forbidden)
// ---------------------------------------------------------------------------
__device__ __align__(1024) __half g_as[(size_t)2 * MTOT * KDIM];   // A split [2][M][512]
__device__ __align__(1024) __half g_bq[(size_t)2 * QKV3 * KDIM];   // w_qkv^T split [2][1536][512]
__device__ __align__(1024) __half g_bo[(size_t)2 * DIMM * KDIM];   // w_out^T split [2][512][512]
__device__ __align__(1024) float  g_qkv[(size_t)MTOT * QKV3];      // qkv fp32

// ---------------------------------------------------------------------------
// PTX helpers (sm_100 base-target safe: cp.async / ldmatrix / mma.sync only)
// ---------------------------------------------------------------------------
__device__ __forceinline__ uint32_t smem_to_u32(const void* p) {
    uint32_t a;
    asm("{ .reg .u64 t; cvta.to.shared.u64 t, %1; cvt.u32.u64 %0, t; }" : "=r"(a) : "l"(p));
    return a;
}
__device__ __forceinline__ void cp_async16(uint32_t dst, const void* src) {
    asm volatile("cp.async.cg.shared.global [%0], [%1], 16;" :: "r"(dst), "l"(src));
}
#define CP_ASYNC_COMMIT() asm volatile("cp.async.commit_group;" ::: "memory")
#define CP_ASYNC_WAIT2()  asm volatile("cp.async.wait_group 2;" ::: "memory")

__device__ __forceinline__ void ldsm4(uint32_t& a, uint32_t& b, uint32_t& c, uint32_t& d,
                                      uint32_t addr) {
    asm volatile("ldmatrix.sync.aligned.m8n8.x4.shared.b16 {%0,%1,%2,%3}, [%4];"
                 : "=r"(a), "=r"(b), "=r"(c), "=r"(d) : "r"(addr));
}
__device__ __forceinline__ void mma16816(float* c, const uint32_t* a,
                                         uint32_t b0, uint32_t b1) {
    asm volatile("mma.sync.aligned.m16n8k16.row.col.f32.f16.f16.f32 "
                 "{%0,%1,%2,%3}, {%4,%5,%6,%7}, {%8,%9}, {%0,%1,%2,%3};"
                 : "+f"(c[0]), "+f"(c[1]), "+f"(c[2]), "+f"(c[3])
                 : "r"(a[0]), "r"(a[1]), "r"(a[2]), "r"(a[3]), "r"(b0), "r"(b1));
}

// ---------------------------------------------------------------------------
// fp16x3 GEMM: C[M,Ng] = A_f32 @ Bw via split operands.
// A_split [2][M][512] (hi,lo) row-major; B_split [2][Ng][512] K-major (hi,lo).
// Virtual K' groups: 0: Ah*Bh, 1: Ah*Bl, 2: Al*Bh.  (dropped terms ~2^-22)
// Tile 128x128, BK=64, 256 threads, 8 warps (4M x 2N), warp tile 32x64.
// ---------------------------------------------------------------------------
__global__ void __launch_bounds__(256)
gemm_f16x3(const __half* __restrict__ A, const __half* __restrict__ B,
           float* __restrict__ C, const float* __restrict__ bias,
           int M, int Ng, int n_tiles)
{
    extern __shared__ char smem_raw[];
    const uint32_t sbase = (smem_to_u32(smem_raw) + 1023u) & ~1023u;
    const int tid  = threadIdx.x;
    const int lane = tid & 31;
    const int wid  = tid >> 5;
    const int m_tile = blockIdx.x / n_tiles;
    const int n_tile = blockIdx.x % n_tiles;
    const int m_base = m_tile * 128;
    const int n_base = n_tile * 128;
    const int m0 = (wid & 3) * 32;     // warp M offset in tile
    const int n0 = (wid >> 2) * 64;    // warp N offset in tile

    // stage-load mapping: thread t loads row t/2 (A and B), 4 x 16B chunks each
    const int ldRow = tid >> 1;
    const int ldC0  = (tid & 1) * 4;

    // ldmatrix lane address components
    const int a_row = lane & 15;              // row within m16 tile
    const int a_kc  = lane >> 4;              // 0/1 -> k 16B chunk within k16
    const int b_row = (lane & 7) + ((lane >> 4) << 3);  // row within n16 tile
    const int b_kc  = (lane >> 3) & 1;

    float acc[2][8][4];
    #pragma unroll
    for (int i = 0; i < 2; i++)
        #pragma unroll
        for (int j = 0; j < 8; j++)
            #pragma unroll
            for (int k = 0; k < 4; k++) acc[i][j][k] = 0.f;

    auto load_stage = [&](int s) {
        const int g  = s >> 3;
        const int k0 = (s & 7) * 64;
        const int az = (g == 2) ? 1 : 0;
        const int bz = (g == 1) ? 1 : 0;
        const uint32_t sa = sbase + (uint32_t)(s & 3) * STAGE_BYTES;
        const uint32_t sb = sa + 16384;
        const __half* ag = A + ((size_t)az * M  + m_base + ldRow) * KDIM + k0;
        const __half* bg = B + ((size_t)bz * Ng + n_base + ldRow) * KDIM + k0;
        #pragma unroll
        for (int j = 0; j < 4; j++) {
            const int c = ldC0 + j;
            const uint32_t off = SMEM_SWIZZLE_128B((uint32_t)(ldRow * 128 + c * 16));
            cp_async16(sa + off, ag + c * 8);
            cp_async16(sb + off, bg + c * 8);
        }
    };

    // prologue: stages 0..2
    #pragma unroll
    for (int s = 0; s < NSTAGES - 1; s++) { load_stage(s); CP_ASYNC_COMMIT(); }

    for (int i = 0; i < KSTEPS; i++) {
        CP_ASYNC_WAIT2();
        __syncthreads();
        if (i + NSTAGES - 1 < KSTEPS) load_stage(i + NSTAGES - 1);
        CP_ASYNC_COMMIT();

        const uint32_t sa = sbase + (uint32_t)(i & 3) * STAGE_BYTES;
        const uint32_t sb = sa + 16384;
        #pragma unroll
        for (int ks = 0; ks < 4; ks++) {
            uint32_t af[2][4];
            uint32_t bf[4][4];
            #pragma unroll
            for (int mt = 0; mt < 2; mt++) {
                const uint32_t off = SMEM_SWIZZLE_128B(
                    (uint32_t)((m0 + mt * 16 + a_row) * 128 + (ks * 2 + a_kc) * 16));
                ldsm4(af[mt][0], af[mt][1], af[mt][2], af[mt][3], sa + off);
            }
            #pragma unroll
            for (int j = 0; j < 4; j++) {
                const uint32_t off = SMEM_SWIZZLE_128B(
                    (uint32_t)((n0 + j * 16 + b_row) * 128 + (ks * 2 + b_kc) * 16));
                ldsm4(bf[j][0], bf[j][1], bf[j][2], bf[j][3], sb + off);
            }
            #pragma unroll
            for (int mt = 0; mt < 2; mt++)
                #pragma unroll
                for (int nt = 0; nt < 8; nt++)
                    mma16816(acc[mt][nt], af[mt],
                             bf[nt >> 1][(nt & 1) * 2], bf[nt >> 1][(nt & 1) * 2 + 1]);
        }
    }

    // epilogue: fragment c: thread holds rows (lane/4, lane/4+8), cols (lane%4)*2
    const int rbase = m_base + m0 + (lane >> 2);
    const int cbase = n_base + n0 + (lane & 3) * 2;
    #pragma unroll
    for (int mt = 0; mt < 2; mt++) {
        const size_t r0 = (size_t)(rbase + mt * 16);
        const size_t r1 = r0 + 8;
        #pragma unroll
        for (int nt = 0; nt < 8; nt++) {
            const int col = cbase + nt * 8;
            float b0 = 0.f, b1 = 0.f;
            if (bias != nullptr) { b0 = bias[col]; b1 = bias[col + 1]; }
            float2 v0 = make_float2(acc[mt][nt][0] + b0, acc[mt][nt][1] + b1);
            float2 v1 = make_float2(acc[mt][nt][2] + b0, acc[mt][nt][3] + b1);
            *reinterpret_cast<float2*>(&C[r0 * Ng + col]) = v0;
            *reinterpret_cast<float2*>(&C[r1 * Ng + col]) = v1;
        }
    }
}

// ---------------------------------------------------------------------------
// fp32 -> fp16 hi/lo split (activations, layout preserved)
// ---------------------------------------------------------------------------
__global__ void __launch_bounds__(256)
split_act_kernel(const float* __restrict__ in,
                 __half* __restrict__ hi, __half* __restrict__ lo, int total4)
{
    int idx = blockIdx.x * blockDim.x + threadIdx.x;
    if (idx >= total4) return;
    float4 v = reinterpret_cast<const float4*>(in)[idx];
    __half h0 = __float2half(v.x), h1 = __float2half(v.y);
    __half h2 = __float2half(v.z), h3 = __float2half(v.w);
    __half l0 = __float2half(v.x - __half2float(h0));
    __half l1 = __float2half(v.y - __half2float(h1));
    __half l2 = __float2half(v.z - __half2float(h2));
    __half l3 = __float2half(v.w - __half2float(h3));
    __half2 hA = __halves2half2(h0, h1), hB = __halves2half2(h2, h3);
    __half2 lA = __halves2half2(l0, l1), lB = __halves2half2(l2, l3);
    uint2 hp, lp;
    hp.x = *reinterpret_cast<uint32_t*>(&hA); hp.y = *reinterpret_cast<uint32_t*>(&hB);
    lp.x = *reinterpret_cast<uint32_t*>(&lA); lp.y = *reinterpret_cast<uint32_t*>(&lB);
    reinterpret_cast<uint2*>(hi)[idx] = hp;
    reinterpret_cast<uint2*>(lo)[idx] = lp;
}

// weights [K,N] fp32 -> B_split [2][N][K] fp16 (transposed, K-major)
__global__ void __launch_bounds__(256)
split_w_kernel(const float* __restrict__ w,
               __half* __restrict__ hi, __half* __restrict__ lo, int N)
{
    int idx = blockIdx.x * blockDim.x + threadIdx.x;
    if (idx >= N * KDIM) return;
    int n = idx / KDIM, k = idx - n * KDIM;
    float v = w[(size_t)k * N + n];
    __half h = __float2half(v);
    __half l = __float2half(v - __half2float(h));
    hi[idx] = h;
    lo[idx] = l;
}

// ---------------------------------------------------------------------------
// 3x3 neighborhood attention; writes output directly as fp16 hi/lo split
// into g_as (the A operand of GEMM2). Zero-pad softmax semantics.
// ---------------------------------------------------------------------------
__global__ void __launch_bounds__(256)
attn_kernel()
{
    const int warp = (blockIdx.x * blockDim.x + threadIdx.x) >> 5;
    const int lane = threadIdx.x & 31;

    const int n = warp & (NPOS - 1);
    const int h = (warp >> 12) & (HEADS - 1);
    const int b = warp >> 15;

    const float scale = 0.125f;
    const int d0 = lane * 2;

    const size_t rowbase = ((size_t)(b * NPOS + n)) * QKV3;
    const float2 q2 = *reinterpret_cast<const float2*>(&g_qkv[rowbase + h * HD + d0]);

    const int y = n >> 6;
    const int x = n & 63;

    float dots[9];
    int   nidx[9];
    #pragma unroll
    for (int j = 0; j < 9; j++) {
        const int dy = j / 3 - 1, dx = j % 3 - 1;
        const int yy = y + dy, xx = x + dx;
        const bool ok = ((unsigned)yy < (unsigned)WIMG) && ((unsigned)xx < (unsigned)WIMG);
        const int nn = yy * WIMG + xx;
        nidx[j] = ok ? nn : -1;
        float p = 0.f;
        if (ok) {
            const float2 k2 = *reinterpret_cast<const float2*>(
                &g_qkv[((size_t)(b * NPOS + nn)) * QKV3 + INNER + h * HD + d0]);
            p = q2.x * k2.x + q2.y * k2.y;
        }
        #pragma unroll
        for (int off = 16; off; off >>= 1)
            p += __shfl_xor_sync(0xffffffffu, p, off);
        dots[j] = p * scale;   // exactly 0 for zero-padded OOB neighbors
    }

    float m = dots[0];
    #pragma unroll
    for (int j = 1; j < 9; j++) m = fmaxf(m, dots[j]);
    float e[9];
    float s = 0.f;
    #pragma unroll
    for (int j = 0; j < 9; j++) { e[j] = __expf(dots[j] - m); s += e[j]; }
    const float inv = 1.f / s;

    float2 accv = make_float2(0.f, 0.f);
    #pragma unroll
    for (int j = 0; j < 9; j++) {
        if (nidx[j] >= 0) {
            const float2 v2 = *reinterpret_cast<const float2*>(
                &g_qkv[((size_t)(b * NPOS + nidx[j])) * QKV3 + 2 * INNER + h * HD + d0]);
            const float a = e[j] * inv;
            accv.x += a * v2.x;
            accv.y += a * v2.y;
        }
    }

    // write split fp16 hi/lo directly (fuses the GEMM2 A-split pass)
    const size_t oidx = ((size_t)(b * NPOS + n)) * KDIM + h * HD + d0;
    __half hx = __float2half(accv.x), hy = __float2half(accv.y);
    __half lx = __float2half(accv.x - __half2float(hx));
    __half ly = __float2half(accv.y - __half2float(hy));
    *reinterpret_cast<__half2*>(&g_as[oidx]) = __halves2half2(hx, hy);
    *reinterpret_cast<__half2*>(&g_as[(size_t)MTOT * KDIM + oidx]) = __halves2half2(lx, ly);
}

// ---------------------------------------------------------------------------
// Launch
// ---------------------------------------------------------------------------
extern "C" void kernel_launch(void* const* d_in, const int* in_sizes, int n_in,
                              void* d_out, int out_size)
{
    const float* x     = (const float*)d_in[0];
    const float* w_qkv = (const float*)d_in[1];
    const float* w_out = (const float*)d_in[2];
    const float* b_out = (const float*)d_in[3];
    float* out = (float*)d_out;

    __half *as = nullptr, *bq = nullptr, *bo = nullptr;
    float *qkv = nullptr;
    cudaGetSymbolAddress((void**)&as,  g_as);
    cudaGetSymbolAddress((void**)&bq,  g_bq);
    cudaGetSymbolAddress((void**)&bo,  g_bo);
    cudaGetSymbolAddress((void**)&qkv, g_qkv);

    cudaFuncSetAttribute(gemm_f16x3,
                         cudaFuncAttributeMaxDynamicSharedMemorySize, GEMM_SMEM);

    const size_t Melems = (size_t)MTOT * KDIM;

    // split x -> A hi/lo
    {
        int total4 = (int)(Melems / 4);
        split_act_kernel<<<(total4 + 255) / 256, 256>>>(x, as, as + Melems, total4);
    }
    // split + transpose w_qkv -> [2][1536][512]
    {
        int tot = QKV3 * KDIM;
        split_w_kernel<<<(tot + 255) / 256, 256>>>(w_qkv, bq, bq + (size_t)QKV3 * KDIM, QKV3);
    }
    // GEMM1: qkv = x @ w_qkv   (M=32768, Ng=1536, 12 n-tiles)
    gemm_f16x3<<<256 * 12, 256, GEMM_SMEM>>>(as, bq, qkv, nullptr, MTOT, QKV3, 12);

    // Attention (writes GEMM2's A operand split)
    {
        const int totalWarps = BB * HEADS * NPOS;
        attn_kernel<<<totalWarps / 8, 256>>>();
    }
    // split + transpose w_out -> [2][512][512]
    {
        int tot = DIMM * KDIM;
        split_w_kernel<<<(tot + 255) / 256, 256>>>(w_out, bo, bo + (size_t)DIMM * KDIM, DIMM);
    }
    // GEMM2: out = attn @ w_out + b_out  (M=32768, Ng=512, 4 n-tiles)
    gemm_f16x3<<<256 * 4, 256, GEMM_SMEM>>>(as, bo, out, b_out, MTOT, DIMM, 4);
}

// round 6
// speedup vs baseline: 3.0133x; 1.5880x over previous
#include <cuda_runtime.h>
#include <cuda_fp16.h>
#include <cstdint>

// Problem constants
#define BB     8
#define HEADS  8
#define NPOS   4096          // 64*64
#define WIMG   64
#define HD     64
#define DIMM   512
#define INNER  512
#define QKV3   1536
#define MTOT   (BB * NPOS)   // 32768
#define KDIM   512

#define STAGE_BYTES 32768          // A 16KB + B 16KB (128x64 fp16 each)
#define NSTAGES     3
#define KSTEPS      16             // 2 groups (Ah*Bh, Ah*Bl) * (512/64)
#define GEMM_SMEM   (1024 + NSTAGES * STAGE_BYTES)   // 99328 -> 2 blocks/SM

#define SMEM_SWIZZLE_128B(off) ((off) ^ (((off) >> 3) & 0x70))

// ---------------------------------------------------------------------------
// Scratch (__device__ globals; allocation is forbidden)
// ---------------------------------------------------------------------------
__device__ __align__(1024) __half g_as[(size_t)MTOT * KDIM];       // A hi [M][512]
__device__ __align__(1024) __half g_bq[(size_t)2 * QKV3 * KDIM];   // w_qkv^T split [2][1536][512]
__device__ __align__(1024) __half g_bo[(size_t)2 * DIMM * KDIM];   // w_out^T split [2][512][512]
__device__ __align__(1024) float  g_qkv[(size_t)MTOT * QKV3];      // qkv fp32

// ---------------------------------------------------------------------------
// PTX helpers (sm_100 base-target safe: cp.async / ldmatrix / mma.sync only)
// ---------------------------------------------------------------------------
__device__ __forceinline__ uint32_t smem_to_u32(const void* p) {
    uint32_t a;
    asm("{ .reg .u64 t; cvta.to.shared.u64 t, %1; cvt.u32.u64 %0, t; }" : "=r"(a) : "l"(p));
    return a;
}
__device__ __forceinline__ void cp_async16(uint32_t dst, const void* src) {
    asm volatile("cp.async.cg.shared.global [%0], [%1], 16;" :: "r"(dst), "l"(src));
}
#define CP_ASYNC_COMMIT() asm volatile("cp.async.commit_group;" ::: "memory")
#define CP_ASYNC_WAIT1()  asm volatile("cp.async.wait_group 1;" ::: "memory")

__device__ __forceinline__ void ldsm4(uint32_t& a, uint32_t& b, uint32_t& c, uint32_t& d,
                                      uint32_t addr) {
    asm volatile("ldmatrix.sync.aligned.m8n8.x4.shared.b16 {%0,%1,%2,%3}, [%4];"
                 : "=r"(a), "=r"(b), "=r"(c), "=r"(d) : "r"(addr));
}
__device__ __forceinline__ void mma16816(float* c, const uint32_t* a,
                                         uint32_t b0, uint32_t b1) {
    asm volatile("mma.sync.aligned.m16n8k16.row.col.f32.f16.f16.f32 "
                 "{%0,%1,%2,%3}, {%4,%5,%6,%7}, {%8,%9}, {%0,%1,%2,%3};"
                 : "+f"(c[0]), "+f"(c[1]), "+f"(c[2]), "+f"(c[3])
                 : "r"(a[0]), "r"(a[1]), "r"(a[2]), "r"(a[3]), "r"(b0), "r"(b1));
}

// ---------------------------------------------------------------------------
// fp16x2 GEMM: C = A_f32 @ Bw with A ~ Ah, B ~ Bh + Bl (Al*B term dropped,
// rel err ~3e-4 << 1e-3). A hi [M][512] row-major; B split [2][Ng][512]
// K-major.  Virtual K' groups: 0: Ah*Bh, 1: Ah*Bl.
// Tile 128x128, BK=64, 256 threads, 8 warps (4M x 2N), warp tile 32x64.
// 3 smem stages (2 blocks/SM) + register-level fragment pipelining.
// ---------------------------------------------------------------------------
__global__ void __launch_bounds__(256, 2)
gemm_f16x2(const __half* __restrict__ A, const __half* __restrict__ B,
           float* __restrict__ C, const float* __restrict__ bias,
           int Ng, int n_tiles)
{
    extern __shared__ char smem_raw[];
    const uint32_t sbase = (smem_to_u32(smem_raw) + 1023u) & ~1023u;
    const int tid  = threadIdx.x;
    const int lane = tid & 31;
    const int wid  = tid >> 5;
    const int m_tile = blockIdx.x / n_tiles;
    const int n_tile = blockIdx.x % n_tiles;
    const int m_base = m_tile * 128;
    const int n_base = n_tile * 128;
    const int m0 = (wid & 3) * 32;     // warp M offset in tile
    const int n0 = (wid >> 2) * 64;    // warp N offset in tile

    // stage-load mapping: thread t loads row t/2 (A and B), 4 x 16B chunks each
    const int ldRow = tid >> 1;
    const int ldC0  = (tid & 1) * 4;

    // ldmatrix lane address components
    const int a_row = lane & 15;
    const int a_kc  = lane >> 4;
    const int b_row = (lane & 7) + ((lane >> 4) << 3);
    const int b_kc  = (lane >> 3) & 1;

    float acc[2][8][4];
    #pragma unroll
    for (int i = 0; i < 2; i++)
        #pragma unroll
        for (int j = 0; j < 8; j++)
            #pragma unroll
            for (int k = 0; k < 4; k++) acc[i][j][k] = 0.f;

    auto load_stage = [&](int s) {
        const int bz = s >> 3;             // group: 0 = Bh, 1 = Bl
        const int k0 = (s & 7) * 64;
        const uint32_t sa = sbase + (uint32_t)(s % NSTAGES) * STAGE_BYTES;
        const uint32_t sb = sa + 16384;
        const __half* ag = A + ((size_t)(m_base + ldRow)) * KDIM + k0;
        const __half* bg = B + ((size_t)bz * Ng + n_base + ldRow) * KDIM + k0;
        #pragma unroll
        for (int j = 0; j < 4; j++) {
            const int c = ldC0 + j;
            const uint32_t off = SMEM_SWIZZLE_128B((uint32_t)(ldRow * 128 + c * 16));
            cp_async16(sa + off, ag + c * 8);
            cp_async16(sb + off, bg + c * 8);
        }
    };

    // prologue: stages 0..1
    #pragma unroll
    for (int s = 0; s < NSTAGES - 1; s++) { load_stage(s); CP_ASYNC_COMMIT(); }

    for (int i = 0; i < KSTEPS; i++) {
        CP_ASYNC_WAIT1();
        __syncthreads();
        if (i + NSTAGES - 1 < KSTEPS) load_stage(i + NSTAGES - 1);
        CP_ASYNC_COMMIT();

        const uint32_t sa = sbase + (uint32_t)(i % NSTAGES) * STAGE_BYTES;
        const uint32_t sb = sa + 16384;

        uint32_t af[2][2][4];   // [buf][mt][4]
        uint32_t bf[2][4];      // [buf][4]

        auto lda = [&](uint32_t* dst, int mt, int ks) {
            const uint32_t off = SMEM_SWIZZLE_128B(
                (uint32_t)((m0 + mt * 16 + a_row) * 128 + (ks * 2 + a_kc) * 16));
            ldsm4(dst[0], dst[1], dst[2], dst[3], sa + off);
        };
        auto ldb = [&](uint32_t* dst, int ks, int j) {
            const uint32_t off = SMEM_SWIZZLE_128B(
                (uint32_t)((n0 + j * 16 + b_row) * 128 + (ks * 2 + b_kc) * 16));
            ldsm4(dst[0], dst[1], dst[2], dst[3], sb + off);
        };

        // preload ks=0 fragments
        lda(af[0][0], 0, 0);
        lda(af[0][1], 1, 0);
        ldb(bf[0], 0, 0);

        #pragma unroll
        for (int ks = 0; ks < 4; ks++) {
            const int ab = ks & 1;
            #pragma unroll
            for (int j = 0; j < 4; j++) {
                const int bb = j & 1;
                // prefetch next B fragment
                if (j < 3)       ldb(bf[bb ^ 1], ks, j + 1);
                else if (ks < 3) ldb(bf[bb ^ 1], ks + 1, 0);
                // prefetch next A fragments mid-group
                if (j == 1 && ks < 3) lda(af[ab ^ 1][0], 0, ks + 1);
                if (j == 2 && ks < 3) lda(af[ab ^ 1][1], 1, ks + 1);
                // 4 mma using current fragments (nt = 2j, 2j+1)
                #pragma unroll
                for (int mt = 0; mt < 2; mt++) {
                    mma16816(acc[mt][2 * j],     af[ab][mt], bf[bb][0], bf[bb][1]);
                    mma16816(acc[mt][2 * j + 1], af[ab][mt], bf[bb][2], bf[bb][3]);
                }
            }
        }
    }

    // epilogue
    const int rbase = m_base + m0 + (lane >> 2);
    const int cbase = n_base + n0 + (lane & 3) * 2;
    #pragma unroll
    for (int mt = 0; mt < 2; mt++) {
        const size_t r0 = (size_t)(rbase + mt * 16);
        const size_t r1 = r0 + 8;
        #pragma unroll
        for (int nt = 0; nt < 8; nt++) {
            const int col = cbase + nt * 8;
            float b0 = 0.f, b1 = 0.f;
            if (bias != nullptr) { b0 = bias[col]; b1 = bias[col + 1]; }
            float2 v0 = make_float2(acc[mt][nt][0] + b0, acc[mt][nt][1] + b1);
            float2 v1 = make_float2(acc[mt][nt][2] + b0, acc[mt][nt][3] + b1);
            *reinterpret_cast<float2*>(&C[r0 * Ng + col]) = v0;
            *reinterpret_cast<float2*>(&C[r1 * Ng + col]) = v1;
        }
    }
}

// ---------------------------------------------------------------------------
// fp32 -> fp16 convert (hi only; Al term dropped from GEMM)
// ---------------------------------------------------------------------------
__global__ void __launch_bounds__(256)
conv_act_kernel(const float* __restrict__ in, __half* __restrict__ hi, int total4)
{
    int idx = blockIdx.x * blockDim.x + threadIdx.x;
    if (idx >= total4) return;
    float4 v = reinterpret_cast<const float4*>(in)[idx];
    __half2 hA = __halves2half2(__float2half(v.x), __float2half(v.y));
    __half2 hB = __halves2half2(__float2half(v.z), __float2half(v.w));
    uint2 hp;
    hp.x = *reinterpret_cast<uint32_t*>(&hA);
    hp.y = *reinterpret_cast<uint32_t*>(&hB);
    reinterpret_cast<uint2*>(hi)[idx] = hp;
}

// weights [K,N] fp32 -> B_split [2][N][K] fp16 (transposed, K-major, hi+lo)
__global__ void __launch_bounds__(256)
split_w_kernel(const float* __restrict__ w,
               __half* __restrict__ hi, __half* __restrict__ lo, int N)
{
    int idx = blockIdx.x * blockDim.x + threadIdx.x;
    if (idx >= N * KDIM) return;
    int n = idx / KDIM, k = idx - n * KDIM;
    float v = w[(size_t)k * N + n];
    __half h = __float2half(v);
    __half l = __float2half(v - __half2float(h));
    hi[idx] = h;
    lo[idx] = l;
}

// ---------------------------------------------------------------------------
// 3x3 neighborhood attention; writes fp16 hi directly into g_as (GEMM2's A).
// Zero-pad softmax semantics. All addressing 32-bit.
// ---------------------------------------------------------------------------
__global__ void __launch_bounds__(256)
attn_kernel()
{
    const int warp = (blockIdx.x * blockDim.x + threadIdx.x) >> 5;
    const int lane = threadIdx.x & 31;

    const int n = warp & (NPOS - 1);
    const int h = (warp >> 12) & (HEADS - 1);
    const int b = warp >> 15;

    const float scale = 0.125f;
    const int d0 = lane * 2;

    const uint32_t hoff  = (uint32_t)(h * HD + d0);
    const uint32_t row   = (uint32_t)(b * NPOS + n);
    const uint32_t kbase = (uint32_t)(b * NPOS) * QKV3 + INNER + hoff;

    const float2 q2 = *reinterpret_cast<const float2*>(&g_qkv[row * QKV3 + hoff]);

    const int y = n >> 6;
    const int x = n & 63;

    float dots[9];
    uint32_t koff[9];
    uint32_t okm = 0;
    #pragma unroll
    for (int j = 0; j < 9; j++) {
        const int dy = j / 3 - 1, dx = j % 3 - 1;
        const int yy = y + dy, xx = x + dx;
        const bool ok = ((unsigned)yy < (unsigned)WIMG) && ((unsigned)xx < (unsigned)WIMG);
        const uint32_t nn = (uint32_t)(yy * WIMG + xx);
        koff[j] = kbase + nn * QKV3;
        if (ok) okm |= (1u << j);
        float p = 0.f;
        if (ok) {
            const float2 k2 = *reinterpret_cast<const float2*>(&g_qkv[koff[j]]);
            p = q2.x * k2.x + q2.y * k2.y;
        }
        #pragma unroll
        for (int off = 16; off; off >>= 1)
            p += __shfl_xor_sync(0xffffffffu, p, off);
        dots[j] = p * scale;   // exactly 0 for zero-padded OOB neighbors
    }

    float m = dots[0];
    #pragma unroll
    for (int j = 1; j < 9; j++) m = fmaxf(m, dots[j]);
    float e[9];
    float s = 0.f;
    #pragma unroll
    for (int j = 0; j < 9; j++) { e[j] = __expf(dots[j] - m); s += e[j]; }
    const float inv = 1.f / s;

    float2 accv = make_float2(0.f, 0.f);
    #pragma unroll
    for (int j = 0; j < 9; j++) {
        if (okm & (1u << j)) {
            const float2 v2 = *reinterpret_cast<const float2*>(&g_qkv[koff[j] + INNER]);
            const float a = e[j] * inv;
            accv.x += a * v2.x;
            accv.y += a * v2.y;
        }
    }

    const uint32_t oidx = row * KDIM + hoff;
    *reinterpret_cast<__half2*>(&g_as[oidx]) =
        __halves2half2(__float2half(accv.x), __float2half(accv.y));
}

// ---------------------------------------------------------------------------
// Launch
// ---------------------------------------------------------------------------
extern "C" void kernel_launch(void* const* d_in, const int* in_sizes, int n_in,
                              void* d_out, int out_size)
{
    const float* x     = (const float*)d_in[0];
    const float* w_qkv = (const float*)d_in[1];
    const float* w_out = (const float*)d_in[2];
    const float* b_out = (const float*)d_in[3];
    float* out = (float*)d_out;

    __half *as = nullptr, *bq = nullptr, *bo = nullptr;
    float *qkv = nullptr;
    cudaGetSymbolAddress((void**)&as,  g_as);
    cudaGetSymbolAddress((void**)&bq,  g_bq);
    cudaGetSymbolAddress((void**)&bo,  g_bo);
    cudaGetSymbolAddress((void**)&qkv, g_qkv);

    cudaFuncSetAttribute(gemm_f16x2,
                         cudaFuncAttributeMaxDynamicSharedMemorySize, GEMM_SMEM);

    const size_t Melems = (size_t)MTOT * KDIM;

    // convert x -> A hi
    {
        int total4 = (int)(Melems / 4);
        conv_act_kernel<<<(total4 + 255) / 256, 256>>>(x, as, total4);
    }
    // split + transpose w_qkv -> [2][1536][512]
    {
        int tot = QKV3 * KDIM;
        split_w_kernel<<<(tot + 255) / 256, 256>>>(w_qkv, bq, bq + (size_t)QKV3 * KDIM, QKV3);
    }
    // GEMM1: qkv = x @ w_qkv   (M=32768, Ng=1536, 12 n-tiles)
    gemm_f16x2<<<256 * 12, 256, GEMM_SMEM>>>(as, bq, qkv, nullptr, QKV3, 12);

    // Attention (writes GEMM2's A operand, fp16 hi)
    {
        const int totalWarps = BB * HEADS * NPOS;
        attn_kernel<<<totalWarps / 8, 256>>>();
    }
    // split + transpose w_out -> [2][512][512]
    {
        int tot = DIMM * KDIM;
        split_w_kernel<<<(tot + 255) / 256, 256>>>(w_out, bo, bo + (size_t)DIMM * KDIM, DIMM);
    }
    // GEMM2: out = attn @ w_out + b_out  (M=32768, Ng=512, 4 n-tiles)
    gemm_f16x2<<<256 * 4, 256, GEMM_SMEM>>>(as, bo, out, b_out, DIMM, 4);
}

// round 8
// speedup vs baseline: 4.1094x; 1.3637x over previous
#include <cuda_runtime.h>
#include <cuda_fp16.h>
#include <cstdint>

// Problem constants
#define BB     8
#define HEADS  8
#define NPOS   4096          // 64*64
#define WIMG   64
#define HD     64
#define DIMM   512
#define INNER  512
#define QKV3   1536
#define MTOT   (BB * NPOS)   // 32768
#define KDIM   512

#define STAGE_BYTES 32768          // A 16KB + B 16KB (128x64 fp16 each)
#define NSTAGES     3
#define GEMM_SMEM   (1024 + NSTAGES * STAGE_BYTES)   // 99328 -> 2 blocks/SM

#define SMEM_SWIZZLE_128B(off) ((off) ^ (((off) >> 3) & 0x70))

// ---------------------------------------------------------------------------
// Scratch (__device__ globals; allocation is forbidden)
// ---------------------------------------------------------------------------
__device__ __align__(1024) __half g_as[(size_t)MTOT * KDIM];       // A hi [M][512]
__device__ __align__(1024) __half g_bq[(size_t)QKV3 * KDIM];       // w_qkv^T hi [1536][512]
__device__ __align__(1024) __half g_bo[(size_t)2 * DIMM * KDIM];   // w_out^T split [2][512][512]
__device__ __align__(1024) float  g_qkv[(size_t)MTOT * QKV3];      // qkv fp32

// ---------------------------------------------------------------------------
// PTX helpers (sm_100 base-target safe: cp.async / ldmatrix / mma.sync only)
// ---------------------------------------------------------------------------
__device__ __forceinline__ uint32_t smem_to_u32(const void* p) {
    uint32_t a;
    asm("{ .reg .u64 t; cvta.to.shared.u64 t, %1; cvt.u32.u64 %0, t; }" : "=r"(a) : "l"(p));
    return a;
}
__device__ __forceinline__ void cp_async16(uint32_t dst, const void* src) {
    asm volatile("cp.async.cg.shared.global [%0], [%1], 16;" :: "r"(dst), "l"(src));
}
#define CP_ASYNC_COMMIT() asm volatile("cp.async.commit_group;" ::: "memory")
#define CP_ASYNC_WAIT1()  asm volatile("cp.async.wait_group 1;" ::: "memory")

__device__ __forceinline__ void ldsm4(uint32_t& a, uint32_t& b, uint32_t& c, uint32_t& d,
                                      uint32_t addr) {
    asm volatile("ldmatrix.sync.aligned.m8n8.x4.shared.b16 {%0,%1,%2,%3}, [%4];"
                 : "=r"(a), "=r"(b), "=r"(c), "=r"(d) : "r"(addr));
}
__device__ __forceinline__ void mma16816(float* c, const uint32_t* a,
                                         uint32_t b0, uint32_t b1) {
    asm volatile("mma.sync.aligned.m16n8k16.row.col.f32.f16.f16.f32 "
                 "{%0,%1,%2,%3}, {%4,%5,%6,%7}, {%8,%9}, {%0,%1,%2,%3};"
                 : "+f"(c[0]), "+f"(c[1]), "+f"(c[2]), "+f"(c[3])
                 : "r"(a[0]), "r"(a[1]), "r"(a[2]), "r"(a[3]), "r"(b0), "r"(b1));
}

// ---------------------------------------------------------------------------
// fp16 GEMM: C = Ah @ (Bh [+ Bl]).  kgroups = 1 (single pass) or 2 (adds the
// B-lo correction pass for higher precision).  A hi [M][512] row-major;
// B [kgroups][Ng][512] K-major.
// Tile 128x128, BK=64, 256 threads, 8 warps (4M x 2N), warp tile 32x64.
// 3 smem stages (2 blocks/SM) + register-level fragment pipelining.
// ---------------------------------------------------------------------------
__global__ void __launch_bounds__(256, 2)
gemm_f16(const __half* __restrict__ A, const __half* __restrict__ B,
         float* __restrict__ C, const float* __restrict__ bias,
         int Ng, int n_tiles, int kgroups)
{
    extern __shared__ char smem_raw[];
    const uint32_t sbase = (smem_to_u32(smem_raw) + 1023u) & ~1023u;
    const int tid  = threadIdx.x;
    const int lane = tid & 31;
    const int wid  = tid >> 5;
    const int m_tile = blockIdx.x / n_tiles;
    const int n_tile = blockIdx.x % n_tiles;
    const int m_base = m_tile * 128;
    const int n_base = n_tile * 128;
    const int m0 = (wid & 3) * 32;     // warp M offset in tile
    const int n0 = (wid >> 2) * 64;    // warp N offset in tile
    const int ksteps = kgroups * 8;

    // stage-load mapping: thread t loads row t/2 (A and B), 4 x 16B chunks each
    const int ldRow = tid >> 1;
    const int ldC0  = (tid & 1) * 4;

    // ldmatrix lane address components
    const int a_row = lane & 15;
    const int a_kc  = lane >> 4;
    const int b_row = (lane & 7) + ((lane >> 4) << 3);
    const int b_kc  = (lane >> 3) & 1;

    float acc[2][8][4];
    #pragma unroll
    for (int i = 0; i < 2; i++)
        #pragma unroll
        for (int j = 0; j < 8; j++)
            #pragma unroll
            for (int k = 0; k < 4; k++) acc[i][j][k] = 0.f;

    auto load_stage = [&](int s) {
        const int bz = s >> 3;             // group: 0 = Bh, 1 = Bl
        const int k0 = (s & 7) * 64;
        const uint32_t sa = sbase + (uint32_t)(s % NSTAGES) * STAGE_BYTES;
        const uint32_t sb = sa + 16384;
        const __half* ag = A + ((size_t)(m_base + ldRow)) * KDIM + k0;
        const __half* bg = B + ((size_t)bz * Ng + n_base + ldRow) * KDIM + k0;
        #pragma unroll
        for (int j = 0; j < 4; j++) {
            const int c = ldC0 + j;
            const uint32_t off = SMEM_SWIZZLE_128B((uint32_t)(ldRow * 128 + c * 16));
            cp_async16(sa + off, ag + c * 8);
            cp_async16(sb + off, bg + c * 8);
        }
    };

    // prologue: stages 0..1
    #pragma unroll
    for (int s = 0; s < NSTAGES - 1; s++) { load_stage(s); CP_ASYNC_COMMIT(); }

    for (int i = 0; i < ksteps; i++) {
        CP_ASYNC_WAIT1();
        __syncthreads();
        if (i + NSTAGES - 1 < ksteps) load_stage(i + NSTAGES - 1);
        CP_ASYNC_COMMIT();

        const uint32_t sa = sbase + (uint32_t)(i % NSTAGES) * STAGE_BYTES;
        const uint32_t sb = sa + 16384;

        uint32_t af[2][2][4];   // [buf][mt][4]
        uint32_t bf[2][4];      // [buf][4]

        auto lda = [&](uint32_t* dst, int mt, int ks) {
            const uint32_t off = SMEM_SWIZZLE_128B(
                (uint32_t)((m0 + mt * 16 + a_row) * 128 + (ks * 2 + a_kc) * 16));
            ldsm4(dst[0], dst[1], dst[2], dst[3], sa + off);
        };
        auto ldb = [&](uint32_t* dst, int ks, int j) {
            const uint32_t off = SMEM_SWIZZLE_128B(
                (uint32_t)((n0 + j * 16 + b_row) * 128 + (ks * 2 + b_kc) * 16));
            ldsm4(dst[0], dst[1], dst[2], dst[3], sb + off);
        };

        // preload ks=0 fragments
        lda(af[0][0], 0, 0);
        lda(af[0][1], 1, 0);
        ldb(bf[0], 0, 0);

        #pragma unroll
        for (int ks = 0; ks < 4; ks++) {
            const int ab = ks & 1;
            #pragma unroll
            for (int j = 0; j < 4; j++) {
                const int bb = j & 1;
                // prefetch next B fragment
                if (j < 3)       ldb(bf[bb ^ 1], ks, j + 1);
                else if (ks < 3) ldb(bf[bb ^ 1], ks + 1, 0);
                // prefetch next A fragments mid-group
                if (j == 1 && ks < 3) lda(af[ab ^ 1][0], 0, ks + 1);
                if (j == 2 && ks < 3) lda(af[ab ^ 1][1], 1, ks + 1);
                // 4 mma using current fragments (nt = 2j, 2j+1)
                #pragma unroll
                for (int mt = 0; mt < 2; mt++) {
                    mma16816(acc[mt][2 * j],     af[ab][mt], bf[bb][0], bf[bb][1]);
                    mma16816(acc[mt][2 * j + 1], af[ab][mt], bf[bb][2], bf[bb][3]);
                }
            }
        }
    }

    // epilogue
    const int rbase = m_base + m0 + (lane >> 2);
    const int cbase = n_base + n0 + (lane & 3) * 2;
    #pragma unroll
    for (int mt = 0; mt < 2; mt++) {
        const size_t r0 = (size_t)(rbase + mt * 16);
        const size_t r1 = r0 + 8;
        #pragma unroll
        for (int nt = 0; nt < 8; nt++) {
            const int col = cbase + nt * 8;
            float b0 = 0.f, b1 = 0.f;
            if (bias != nullptr) { b0 = bias[col]; b1 = bias[col + 1]; }
            float2 v0 = make_float2(acc[mt][nt][0] + b0, acc[mt][nt][1] + b1);
            float2 v1 = make_float2(acc[mt][nt][2] + b0, acc[mt][nt][3] + b1);
            *reinterpret_cast<float2*>(&C[r0 * Ng + col]) = v0;
            *reinterpret_cast<float2*>(&C[r1 * Ng + col]) = v1;
        }
    }
}

// ---------------------------------------------------------------------------
// fp32 -> fp16 convert (hi only)
// ---------------------------------------------------------------------------
__global__ void __launch_bounds__(256)
conv_act_kernel(const float* __restrict__ in, __half* __restrict__ hi, int total4)
{
    int idx = blockIdx.x * blockDim.x + threadIdx.x;
    if (idx >= total4) return;
    float4 v = reinterpret_cast<const float4*>(in)[idx];
    __half2 hA = __halves2half2(__float2half(v.x), __float2half(v.y));
    __half2 hB = __halves2half2(__float2half(v.z), __float2half(v.w));
    uint2 hp;
    hp.x = *reinterpret_cast<uint32_t*>(&hA);
    hp.y = *reinterpret_cast<uint32_t*>(&hB);
    reinterpret_cast<uint2*>(hi)[idx] = hp;
}

// weights [K,N] fp32 -> hi-only transposed [N][K] fp16
__global__ void __launch_bounds__(256)
conv_w_kernel(const float* __restrict__ w, __half* __restrict__ hi, int N)
{
    int idx = blockIdx.x * blockDim.x + threadIdx.x;
    if (idx >= N * KDIM) return;
    int n = idx / KDIM, k = idx - n * KDIM;
    hi[idx] = __float2half(w[(size_t)k * N + n]);
}

// weights [K,N] fp32 -> split [2][N][K] fp16 (hi + lo)
__global__ void __launch_bounds__(256)
split_w_kernel(const float* __restrict__ w,
               __half* __restrict__ hi, __half* __restrict__ lo, int N)
{
    int idx = blockIdx.x * blockDim.x + threadIdx.x;
    if (idx >= N * KDIM) return;
    int n = idx / KDIM, k = idx - n * KDIM;
    float v = w[(size_t)k * N + n];
    __half h = __float2half(v);
    __half l = __float2half(v - __half2float(h));
    hi[idx] = h;
    lo[idx] = l;
}

// ---------------------------------------------------------------------------
// 3x3 neighborhood attention. HALF-WARP (16 lanes x float4) per query, two
// queries per warp. Writes fp16 hi directly into g_as (GEMM2's A operand).
// Zero-pad softmax semantics. 32-bit addressing.
// ---------------------------------------------------------------------------
__global__ void __launch_bounds__(256)
attn_kernel()
{
    const int gwarp = (blockIdx.x * blockDim.x + threadIdx.x) >> 5;
    const int lane  = threadIdx.x & 31;
    const int half  = lane >> 4;       // which query of the pair
    const int l16   = lane & 15;

    const int q = gwarp * 2 + half;    // query index: b*32768 + h*4096 + n
    const int n = q & (NPOS - 1);
    const int h = (q >> 12) & (HEADS - 1);
    const int b = q >> 15;

    const float scale = 0.125f;
    const int d0 = l16 * 4;

    const uint32_t hoff  = (uint32_t)(h * HD + d0);
    const uint32_t row   = (uint32_t)(b * NPOS + n);
    const uint32_t kbase = (uint32_t)(b * NPOS) * QKV3 + INNER + hoff;

    const float4 q4 = *reinterpret_cast<const float4*>(&g_qkv[row * QKV3 + hoff]);

    const int y = n >> 6;
    const int x = n & 63;

    float dots[9];
    uint32_t koff[9];
    uint32_t okm = 0;
    #pragma unroll
    for (int j = 0; j < 9; j++) {
        const int dy = j / 3 - 1, dx = j % 3 - 1;
        const int yy = y + dy, xx = x + dx;
        const bool ok = ((unsigned)yy < (unsigned)WIMG) && ((unsigned)xx < (unsigned)WIMG);
        const uint32_t nn = (uint32_t)(yy * WIMG + xx);
        koff[j] = kbase + nn * QKV3;
        if (ok) okm |= (1u << j);
        float p = 0.f;
        if (ok) {
            const float4 k4 = *reinterpret_cast<const float4*>(&g_qkv[koff[j]]);
            p = q4.x * k4.x + q4.y * k4.y + q4.z * k4.z + q4.w * k4.w;
        }
        // reduce within the 16-lane half-warp (xor < 16 stays in-half)
        #pragma unroll
        for (int off = 8; off; off >>= 1)
            p += __shfl_xor_sync(0xffffffffu, p, off);
        dots[j] = p * scale;   // exactly 0 for zero-padded OOB neighbors
    }

    float m = dots[0];
    #pragma unroll
    for (int j = 1; j < 9; j++) m = fmaxf(m, dots[j]);
    float e[9];
    float s = 0.f;
    #pragma unroll
    for (int j = 0; j < 9; j++) { e[j] = __expf(dots[j] - m); s += e[j]; }
    const float inv = 1.f / s;

    float4 accv = make_float4(0.f, 0.f, 0.f, 0.f);
    #pragma unroll
    for (int j = 0; j < 9; j++) {
        if (okm & (1u << j)) {
            const float4 v4 = *reinterpret_cast<const float4*>(&g_qkv[koff[j] + INNER]);
            const float a = e[j] * inv;
            accv.x += a * v4.x;
            accv.y += a * v4.y;
            accv.z += a * v4.z;
            accv.w += a * v4.w;
        }
    }

    const uint32_t oidx = row * KDIM + hoff;
    __half2 o01 = __halves2half2(__float2half(accv.x), __float2half(accv.y));
    __half2 o23 = __halves2half2(__float2half(accv.z), __float2half(accv.w));
    uint2 st;
    st.x = *reinterpret_cast<uint32_t*>(&o01);
    st.y = *reinterpret_cast<uint32_t*>(&o23);
    *reinterpret_cast<uint2*>(&g_as[oidx]) = st;
}

// ---------------------------------------------------------------------------
// Launch
// ---------------------------------------------------------------------------
extern "C" void kernel_launch(void* const* d_in, const int* in_sizes, int n_in,
                              void* d_out, int out_size)
{
    const float* x     = (const float*)d_in[0];
    const float* w_qkv = (const float*)d_in[1];
    const float* w_out = (const float*)d_in[2];
    const float* b_out = (const float*)d_in[3];
    float* out = (float*)d_out;

    __half *as = nullptr, *bq = nullptr, *bo = nullptr;
    float *qkv = nullptr;
    cudaGetSymbolAddress((void**)&as,  g_as);
    cudaGetSymbolAddress((void**)&bq,  g_bq);
    cudaGetSymbolAddress((void**)&bo,  g_bo);
    cudaGetSymbolAddress((void**)&qkv, g_qkv);

    cudaFuncSetAttribute(gemm_f16,
                         cudaFuncAttributeMaxDynamicSharedMemorySize, GEMM_SMEM);

    const size_t Melems = (size_t)MTOT * KDIM;

    // convert x -> A hi
    {
        int total4 = (int)(Melems / 4);
        conv_act_kernel<<<(total4 + 255) / 256, 256>>>(x, as, total4);
    }
    // convert + transpose w_qkv -> hi only [1536][512]
    {
        int tot = QKV3 * KDIM;
        conv_w_kernel<<<(tot + 255) / 256, 256>>>(w_qkv, bq, QKV3);
    }
    // GEMM1 (single pass): qkv = x @ w_qkv   (M=32768, Ng=1536, 12 n-tiles)
    gemm_f16<<<256 * 12, 256, GEMM_SMEM>>>(as, bq, qkv, nullptr, QKV3, 12, 1);

    // Attention (writes GEMM2's A operand, fp16 hi); 2 queries per warp
    {
        const int totalQ = BB * HEADS * NPOS;      // 262144
        attn_kernel<<<totalQ / 16, 256>>>();
    }
    // split + transpose w_out -> [2][512][512]
    {
        int tot = DIMM * KDIM;
        split_w_kernel<<<(tot + 255) / 256, 256>>>(w_out, bo, bo + (size_t)DIMM * KDIM, DIMM);
    }
    // GEMM2 (2-pass): out = attn @ w_out + b_out  (M=32768, Ng=512, 4 n-tiles)
    gemm_f16<<<256 * 4, 256, GEMM_SMEM>>>(as, bo, out, b_out, DIMM, 4, 2);
}

// round 10
// speedup vs baseline: 5.1239x; 1.2469x over previous
#include <cuda_runtime.h>
#include <cuda_fp16.h>
#include <cstdint>

// Problem constants
#define BB     8
#define HEADS  8
#define NPOS   4096          // 64*64
#define WIMG   64
#define HD     64
#define DIMM   512
#define INNER  512
#define QKV3   1536
#define MTOT   (BB * NPOS)   // 32768
#define KDIM   512

#define STAGE_BYTES 32768          // A 16KB + B 16KB (128x64 fp16 each)
#define NSTAGES     3
#define GEMM_SMEM   (1024 + NSTAGES * STAGE_BYTES)   // 99328 -> 2 blocks/SM

#define SMEM_SWIZZLE_128B(off) ((off) ^ (((off) >> 3) & 0x70))

// ---------------------------------------------------------------------------
// Scratch (__device__ globals; allocation is forbidden)
// ---------------------------------------------------------------------------
__device__ __align__(1024) __half g_as[(size_t)MTOT * KDIM];   // A hi [M][512]
__device__ __align__(1024) __half g_bq[(size_t)QKV3 * KDIM];   // w_qkv^T hi [1536][512]
__device__ __align__(1024) __half g_bo[(size_t)DIMM * KDIM];   // w_out^T hi [512][512]
__device__ __align__(1024) __half g_qkv[(size_t)MTOT * QKV3];  // qkv fp16

// ---------------------------------------------------------------------------
// PTX helpers (sm_100 base-target safe: cp.async / ldmatrix / mma.sync only)
// ---------------------------------------------------------------------------
__device__ __forceinline__ uint32_t smem_to_u32(const void* p) {
    uint32_t a;
    asm("{ .reg .u64 t; cvta.to.shared.u64 t, %1; cvt.u32.u64 %0, t; }" : "=r"(a) : "l"(p));
    return a;
}
__device__ __forceinline__ void cp_async16(uint32_t dst, const void* src) {
    asm volatile("cp.async.cg.shared.global [%0], [%1], 16;" :: "r"(dst), "l"(src));
}
#define CP_ASYNC_COMMIT() asm volatile("cp.async.commit_group;" ::: "memory")
#define CP_ASYNC_WAIT1()  asm volatile("cp.async.wait_group 1;" ::: "memory")

__device__ __forceinline__ void ldsm4(uint32_t& a, uint32_t& b, uint32_t& c, uint32_t& d,
                                      uint32_t addr) {
    asm volatile("ldmatrix.sync.aligned.m8n8.x4.shared.b16 {%0,%1,%2,%3}, [%4];"
                 : "=r"(a), "=r"(b), "=r"(c), "=r"(d) : "r"(addr));
}
__device__ __forceinline__ void mma16816(float* c, const uint32_t* a,
                                         uint32_t b0, uint32_t b1) {
    asm volatile("mma.sync.aligned.m16n8k16.row.col.f32.f16.f16.f32 "
                 "{%0,%1,%2,%3}, {%4,%5,%6,%7}, {%8,%9}, {%0,%1,%2,%3};"
                 : "+f"(c[0]), "+f"(c[1]), "+f"(c[2]), "+f"(c[3])
                 : "r"(a[0]), "r"(a[1]), "r"(a[2]), "r"(a[3]), "r"(b0), "r"(b1));
}

// ---------------------------------------------------------------------------
// fp16 GEMM: C = Ah @ Bh (single pass).  A hi [M][512] row-major;
// B [Ng][512] K-major.  Output fp32 (+bias) or fp16 (half_out).
// Tile 128x128, BK=64, 256 threads, 8 warps (4M x 2N), warp tile 32x64.
// 3 smem stages (2 blocks/SM) + register-level fragment pipelining.
// ---------------------------------------------------------------------------
__global__ void __launch_bounds__(256, 2)
gemm_f16(const __half* __restrict__ A, const __half* __restrict__ B,
         void* __restrict__ Cout, const float* __restrict__ bias,
         int Ng, int n_tiles, int half_out)
{
    extern __shared__ char smem_raw[];
    const uint32_t sbase = (smem_to_u32(smem_raw) + 1023u) & ~1023u;
    const int tid  = threadIdx.x;
    const int lane = tid & 31;
    const int wid  = tid >> 5;
    const int m_tile = blockIdx.x / n_tiles;
    const int n_tile = blockIdx.x % n_tiles;
    const int m_base = m_tile * 128;
    const int n_base = n_tile * 128;
    const int m0 = (wid & 3) * 32;     // warp M offset in tile
    const int n0 = (wid >> 2) * 64;    // warp N offset in tile
    const int ksteps = 8;              // 512 / 64

    // stage-load mapping: thread t loads row t/2 (A and B), 4 x 16B chunks each
    const int ldRow = tid >> 1;
    const int ldC0  = (tid & 1) * 4;

    // ldmatrix lane address components
    const int a_row = lane & 15;
    const int a_kc  = lane >> 4;
    const int b_row = (lane & 7) + ((lane >> 4) << 3);
    const int b_kc  = (lane >> 3) & 1;

    float acc[2][8][4];
    #pragma unroll
    for (int i = 0; i < 2; i++)
        #pragma unroll
        for (int j = 0; j < 8; j++)
            #pragma unroll
            for (int k = 0; k < 4; k++) acc[i][j][k] = 0.f;

    auto load_stage = [&](int s) {
        const int k0 = s * 64;
        const uint32_t sa = sbase + (uint32_t)(s % NSTAGES) * STAGE_BYTES;
        const uint32_t sb = sa + 16384;
        const __half* ag = A + ((size_t)(m_base + ldRow)) * KDIM + k0;
        const __half* bg = B + ((size_t)(n_base + ldRow)) * KDIM + k0;
        #pragma unroll
        for (int j = 0; j < 4; j++) {
            const int c = ldC0 + j;
            const uint32_t off = SMEM_SWIZZLE_128B((uint32_t)(ldRow * 128 + c * 16));
            cp_async16(sa + off, ag + c * 8);
            cp_async16(sb + off, bg + c * 8);
        }
    };

    // prologue: stages 0..1
    #pragma unroll
    for (int s = 0; s < NSTAGES - 1; s++) { load_stage(s); CP_ASYNC_COMMIT(); }

    for (int i = 0; i < ksteps; i++) {
        CP_ASYNC_WAIT1();
        __syncthreads();
        if (i + NSTAGES - 1 < ksteps) load_stage(i + NSTAGES - 1);
        CP_ASYNC_COMMIT();

        const uint32_t sa = sbase + (uint32_t)(i % NSTAGES) * STAGE_BYTES;
        const uint32_t sb = sa + 16384;

        uint32_t af[2][2][4];   // [buf][mt][4]
        uint32_t bf[2][4];      // [buf][4]

        auto lda = [&](uint32_t* dst, int mt, int ks) {
            const uint32_t off = SMEM_SWIZZLE_128B(
                (uint32_t)((m0 + mt * 16 + a_row) * 128 + (ks * 2 + a_kc) * 16));
            ldsm4(dst[0], dst[1], dst[2], dst[3], sa + off);
        };
        auto ldb = [&](uint32_t* dst, int ks, int j) {
            const uint32_t off = SMEM_SWIZZLE_128B(
                (uint32_t)((n0 + j * 16 + b_row) * 128 + (ks * 2 + b_kc) * 16));
            ldsm4(dst[0], dst[1], dst[2], dst[3], sb + off);
        };

        // preload ks=0 fragments
        lda(af[0][0], 0, 0);
        lda(af[0][1], 1, 0);
        ldb(bf[0], 0, 0);

        #pragma unroll
        for (int ks = 0; ks < 4; ks++) {
            const int ab = ks & 1;
            #pragma unroll
            for (int j = 0; j < 4; j++) {
                const int bb = j & 1;
                // prefetch next B fragment
                if (j < 3)       ldb(bf[bb ^ 1], ks, j + 1);
                else if (ks < 3) ldb(bf[bb ^ 1], ks + 1, 0);
                // prefetch next A fragments mid-group
                if (j == 1 && ks < 3) lda(af[ab ^ 1][0], 0, ks + 1);
                if (j == 2 && ks < 3) lda(af[ab ^ 1][1], 1, ks + 1);
                // 4 mma using current fragments (nt = 2j, 2j+1)
                #pragma unroll
                for (int mt = 0; mt < 2; mt++) {
                    mma16816(acc[mt][2 * j],     af[ab][mt], bf[bb][0], bf[bb][1]);
                    mma16816(acc[mt][2 * j + 1], af[ab][mt], bf[bb][2], bf[bb][3]);
                }
            }
        }
    }

    // epilogue
    const int rbase = m_base + m0 + (lane >> 2);
    const int cbase = n_base + n0 + (lane & 3) * 2;
    if (half_out) {
        __half* Ch = (__half*)Cout;
        #pragma unroll
        for (int mt = 0; mt < 2; mt++) {
            const size_t r0 = (size_t)(rbase + mt * 16);
            const size_t r1 = r0 + 8;
            #pragma unroll
            for (int nt = 0; nt < 8; nt++) {
                const int col = cbase + nt * 8;
                *reinterpret_cast<__half2*>(&Ch[r0 * Ng + col]) =
                    __floats2half2_rn(acc[mt][nt][0], acc[mt][nt][1]);
                *reinterpret_cast<__half2*>(&Ch[r1 * Ng + col]) =
                    __floats2half2_rn(acc[mt][nt][2], acc[mt][nt][3]);
            }
        }
    } else {
        float* C = (float*)Cout;
        #pragma unroll
        for (int mt = 0; mt < 2; mt++) {
            const size_t r0 = (size_t)(rbase + mt * 16);
            const size_t r1 = r0 + 8;
            #pragma unroll
            for (int nt = 0; nt < 8; nt++) {
                const int col = cbase + nt * 8;
                float b0 = 0.f, b1 = 0.f;
                if (bias != nullptr) { b0 = bias[col]; b1 = bias[col + 1]; }
                float2 v0 = make_float2(acc[mt][nt][0] + b0, acc[mt][nt][1] + b1);
                float2 v1 = make_float2(acc[mt][nt][2] + b0, acc[mt][nt][3] + b1);
                *reinterpret_cast<float2*>(&C[r0 * Ng + col]) = v0;
                *reinterpret_cast<float2*>(&C[r1 * Ng + col]) = v1;
            }
        }
    }
}

// ---------------------------------------------------------------------------
// fp32 -> fp16 convert (activations, layout preserved)
// ---------------------------------------------------------------------------
__global__ void __launch_bounds__(256)
conv_act_kernel(const float* __restrict__ in, __half* __restrict__ hi, int total4)
{
    int idx = blockIdx.x * blockDim.x + threadIdx.x;
    if (idx >= total4) return;
    float4 v = reinterpret_cast<const float4*>(in)[idx];
    __half2 hA = __floats2half2_rn(v.x, v.y);
    __half2 hB = __floats2half2_rn(v.z, v.w);
    uint2 hp;
    hp.x = *reinterpret_cast<uint32_t*>(&hA);
    hp.y = *reinterpret_cast<uint32_t*>(&hB);
    reinterpret_cast<uint2*>(hi)[idx] = hp;
}

// weights [K,N] fp32 -> hi-only transposed [N][K] fp16
__global__ void __launch_bounds__(256)
conv_w_kernel(const float* __restrict__ w, __half* __restrict__ hi, int N)
{
    int idx = blockIdx.x * blockDim.x + threadIdx.x;
    if (idx >= N * KDIM) return;
    int n = idx / KDIM, k = idx - n * KDIM;
    hi[idx] = __float2half(w[(size_t)k * N + n]);
}

// ---------------------------------------------------------------------------
// 3x3 neighborhood attention over fp16 qkv. HALF-WARP (16 lanes x 4 dims)
// per query, two queries per warp. Writes fp16 into g_as (GEMM2's A).
// Zero-pad softmax semantics. 32-bit addressing.
// ---------------------------------------------------------------------------
__device__ __forceinline__ float4 ld_h4(const __half* p) {
    const uint2 r = *reinterpret_cast<const uint2*>(p);
    const __half2 h01 = *reinterpret_cast<const __half2*>(&r.x);
    const __half2 h23 = *reinterpret_cast<const __half2*>(&r.y);
    const float2 f01 = __half22float2(h01);
    const float2 f23 = __half22float2(h23);
    return make_float4(f01.x, f01.y, f23.x, f23.y);
}

__global__ void __launch_bounds__(256)
attn_kernel()
{
    const int gwarp = (blockIdx.x * blockDim.x + threadIdx.x) >> 5;
    const int lane  = threadIdx.x & 31;
    const int half  = lane >> 4;       // which query of the pair
    const int l16   = lane & 15;

    const int q = gwarp * 2 + half;    // query index: b*32768 + h*4096 + n
    const int n = q & (NPOS - 1);
    const int h = (q >> 12) & (HEADS - 1);
    const int b = q >> 15;

    const float scale = 0.125f;
    const int d0 = l16 * 4;

    const uint32_t hoff  = (uint32_t)(h * HD + d0);
    const uint32_t row   = (uint32_t)(b * NPOS + n);
    const uint32_t kbase = (uint32_t)(b * NPOS) * QKV3 + INNER + hoff;

    const float4 q4 = ld_h4(&g_qkv[row * QKV3 + hoff]);

    const int y = n >> 6;
    const int x = n & 63;

    float dots[9];
    uint32_t koff[9];
    uint32_t okm = 0;
    #pragma unroll
    for (int j = 0; j < 9; j++) {
        const int dy = j / 3 - 1, dx = j % 3 - 1;
        const int yy = y + dy, xx = x + dx;
        const bool ok = ((unsigned)yy < (unsigned)WIMG) && ((unsigned)xx < (unsigned)WIMG);
        const uint32_t nn = (uint32_t)(yy * WIMG + xx);
        koff[j] = kbase + nn * QKV3;
        if (ok) okm |= (1u << j);
        float p = 0.f;
        if (ok) {
            const float4 k4 = ld_h4(&g_qkv[koff[j]]);
            p = q4.x * k4.x + q4.y * k4.y + q4.z * k4.z + q4.w * k4.w;
        }
        // reduce within the 16-lane half-warp (xor < 16 stays in-half)
        #pragma unroll
        for (int off = 8; off; off >>= 1)
            p += __shfl_xor_sync(0xffffffffu, p, off);
        dots[j] = p * scale;   // exactly 0 for zero-padded OOB neighbors
    }

    float m = dots[0];
    #pragma unroll
    for (int j = 1; j < 9; j++) m = fmaxf(m, dots[j]);
    float e[9];
    float s = 0.f;
    #pragma unroll
    for (int j = 0; j < 9; j++) { e[j] = __expf(dots[j] - m); s += e[j]; }
    const float inv = 1.f / s;

    float4 accv = make_float4(0.f, 0.f, 0.f, 0.f);
    #pragma unroll
    for (int j = 0; j < 9; j++) {
        if (okm & (1u << j)) {
            const float4 v4 = ld_h4(&g_qkv[koff[j] + INNER]);
            const float a = e[j] * inv;
            accv.x += a * v4.x;
            accv.y += a * v4.y;
            accv.z += a * v4.z;
            accv.w += a * v4.w;
        }
    }

    const uint32_t oidx = row * KDIM + hoff;
    __half2 o01 = __floats2half2_rn(accv.x, accv.y);
    __half2 o23 = __floats2half2_rn(accv.z, accv.w);
    uint2 st;
    st.x = *reinterpret_cast<uint32_t*>(&o01);
    st.y = *reinterpret_cast<uint32_t*>(&o23);
    *reinterpret_cast<uint2*>(&g_as[oidx]) = st;
}

// ---------------------------------------------------------------------------
// Launch
// ---------------------------------------------------------------------------
extern "C" void kernel_launch(void* const* d_in, const int* in_sizes, int n_in,
                              void* d_out, int out_size)
{
    const float* x     = (const float*)d_in[0];
    const float* w_qkv = (const float*)d_in[1];
    const float* w_out = (const float*)d_in[2];
    const float* b_out = (const float*)d_in[3];
    float* out = (float*)d_out;

    __half *as = nullptr, *bq = nullptr, *bo = nullptr, *qkv = nullptr;
    cudaGetSymbolAddress((void**)&as,  g_as);
    cudaGetSymbolAddress((void**)&bq,  g_bq);
    cudaGetSymbolAddress((void**)&bo,  g_bo);
    cudaGetSymbolAddress((void**)&qkv, g_qkv);

    cudaFuncSetAttribute(gemm_f16,
                         cudaFuncAttributeMaxDynamicSharedMemorySize, GEMM_SMEM);

    const size_t Melems = (size_t)MTOT * KDIM;

    // convert x -> A hi
    {
        int total4 = (int)(Melems / 4);
        conv_act_kernel<<<(total4 + 255) / 256, 256>>>(x, as, total4);
    }
    // convert + transpose w_qkv -> [1536][512]
    {
        int tot = QKV3 * KDIM;
        conv_w_kernel<<<(tot + 255) / 256, 256>>>(w_qkv, bq, QKV3);
    }
    // GEMM1: qkv = x @ w_qkv  -> fp16 output  (M=32768, Ng=1536, 12 n-tiles)
    gemm_f16<<<256 * 12, 256, GEMM_SMEM>>>(as, bq, qkv, nullptr, QKV3, 12, 1);

    // Attention (fp16 in/out; writes GEMM2's A operand); 2 queries per warp
    {
        const int totalQ = BB * HEADS * NPOS;      // 262144
        attn_kernel<<<totalQ / 16, 256>>>();
    }
    // convert + transpose w_out -> [512][512]
    {
        int tot = DIMM * KDIM;
        conv_w_kernel<<<(tot + 255) / 256, 256>>>(w_out, bo, DIMM);
    }
    // GEMM2: out = attn @ w_out + b_out  -> fp32  (M=32768, Ng=512, 4 n-tiles)
    gemm_f16<<<256 * 4, 256, GEMM_SMEM>>>(as, bo, out, b_out, DIMM, 4, 0);
}